// round 3
// baseline (speedup 1.0000x reference)
#include <cuda_runtime.h>
#include <stdint.h>

#define D_DIM   256
#define TM      128
#define TN      128
#define KCB     16
#define NCH     (D_DIM / KCB)
#define K_NN    16
#define THREADS 256
#define STR     130          // staging stride (conflict-free)
#define DSTR    129          // dbuf stride (conflict-free scan)

__device__ float g_sq[1 << 17];

// ---------------------------------------------------------------------------
__global__ void sqnorm_kernel(const float* __restrict__ h, int n_rows) {
    int row  = blockIdx.x * 8 + (threadIdx.x >> 5);
    int lane = threadIdx.x & 31;
    if (row >= n_rows) return;
    const float4* h4 = (const float4*)(h + (size_t)row * D_DIM);
    float s = 0.f;
#pragma unroll
    for (int p = 0; p < 2; ++p) {
        float4 v = h4[lane + 32 * p];
        s += v.x * v.x + v.y * v.y + v.z * v.z + v.w * v.w;
    }
#pragma unroll
    for (int o = 16; o > 0; o >>= 1)
        s += __shfl_xor_sync(0xffffffffu, s, o);
    if (lane == 0) g_sq[row] = s;
}

// ---------------------------------------------------------------------------
// 2-CTA/SM fused distance GEMM + top-16.
// A and B staged per 16-k chunk (double buffered, stride-130 k-major).
// Heap in smem (one column per row, lane-owned). dbuf halved (2-phase epi).
// ---------------------------------------------------------------------------
__global__ void __launch_bounds__(THREADS, 2)
knn_kernel(const float* __restrict__ h,
           float* __restrict__ out_d,
           float* __restrict__ out_s,
           float* __restrict__ out_t,
           int L, int write_idx) {
    extern __shared__ float sm[];
    float* As   = sm;                         // [2][KCB][STR]
    float* Bs   = As + 2 * KCB * STR;         // [2][KCB][STR]
    float* dbuf = Bs + 2 * KCB * STR;         // [64][DSTR]
    float* hd   = dbuf + 64 * DSTR;           // [K_NN][TM]
    int*   hix  = (int*)(hd + K_NN * TM);     // [K_NN][TM]
    float* sqi  = (float*)(hix + K_NN * TM);  // [TM]
    float* sqj  = sqi + TM;                   // [TN]

    const int b   = blockIdx.y;
    const int i0  = blockIdx.x * TM;
    const int tid = threadIdx.x;
    const int tx  = tid & 15;
    const int ty  = tid >> 4;
    const float* hb = h + (size_t)b * L * D_DIM;

    if (tid < TM) {
        sqi[tid] = g_sq[(size_t)b * L + i0 + tid];
#pragma unroll
        for (int t = 0; t < K_NN; ++t) { hd[t * TM + tid] = 3.4e38f; hix[t * TM + tid] = 0; }
    }
    float worst0 = 3.4e38f, worst1 = 3.4e38f;

    // staging helpers (2 float4 per thread per operand per chunk)
    const int srow = tid >> 2;      // 0..63 (p adds 64)
    const int sc4  = tid & 3;

    for (int jt = 0; jt < L; jt += TN) {
        if (tid < TN) sqj[tid] = g_sq[(size_t)b * L + jt + tid];

        // stage chunk 0 into buffer 0
#pragma unroll
        for (int p = 0; p < 2; ++p) {
            int row = srow + 64 * p;
            float4 va = *(const float4*)(hb + (size_t)(i0 + row) * D_DIM + sc4 * 4);
            float4 vb = *(const float4*)(hb + (size_t)(jt + row) * D_DIM + sc4 * 4);
            float* Ad = As; float* Bd = Bs;
            Ad[(4 * sc4 + 0) * STR + row] = va.x;
            Ad[(4 * sc4 + 1) * STR + row] = va.y;
            Ad[(4 * sc4 + 2) * STR + row] = va.z;
            Ad[(4 * sc4 + 3) * STR + row] = va.w;
            Bd[(4 * sc4 + 0) * STR + row] = vb.x;
            Bd[(4 * sc4 + 1) * STR + row] = vb.y;
            Bd[(4 * sc4 + 2) * STR + row] = vb.z;
            Bd[(4 * sc4 + 3) * STR + row] = vb.w;
        }

        unsigned long long acc2[8][4];
#pragma unroll
        for (int r = 0; r < 8; ++r)
#pragma unroll
            for (int c = 0; c < 4; ++c) acc2[r][c] = 0ull;

        __syncthreads();

#pragma unroll 1
        for (int ch = 0; ch < NCH; ++ch) {
            const float* Ac = As + (ch & 1) * (KCB * STR);
            const float* Bc = Bs + (ch & 1) * (KCB * STR);

            float4 pa0, pa1, pb0, pb1;
            if (ch < NCH - 1) {
                int kb = (ch + 1) * KCB;
                pa0 = *(const float4*)(hb + (size_t)(i0 + srow)      * D_DIM + kb + sc4 * 4);
                pa1 = *(const float4*)(hb + (size_t)(i0 + srow + 64) * D_DIM + kb + sc4 * 4);
                pb0 = *(const float4*)(hb + (size_t)(jt + srow)      * D_DIM + kb + sc4 * 4);
                pb1 = *(const float4*)(hb + (size_t)(jt + srow + 64) * D_DIM + kb + sc4 * 4);
            }

#pragma unroll
            for (int kk = 0; kk < KCB; ++kk) {
                const float* arow = &Ac[kk * STR + ty];
                unsigned long long a2[8], b2[4];
#pragma unroll
                for (int r = 0; r < 8; ++r) {
                    float a = arow[16 * r];
                    asm("mov.b64 %0, {%1, %1};" : "=l"(a2[r]) : "f"(a));
                }
                const unsigned long long* bp =
                    (const unsigned long long*)&Bc[kk * STR + 2 * tx];
#pragma unroll
                for (int c = 0; c < 4; ++c) b2[c] = bp[16 * c];
#pragma unroll
                for (int r = 0; r < 8; ++r)
#pragma unroll
                    for (int c = 0; c < 4; ++c)
                        asm("fma.rn.f32x2 %0, %1, %2, %0;"
                            : "+l"(acc2[r][c]) : "l"(a2[r]), "l"(b2[c]));
            }

            if (ch < NCH - 1) {
                float* Ad = As + ((ch + 1) & 1) * (KCB * STR);
                float* Bd = Bs + ((ch + 1) & 1) * (KCB * STR);
                Ad[(4 * sc4 + 0) * STR + srow] = pa0.x;
                Ad[(4 * sc4 + 1) * STR + srow] = pa0.y;
                Ad[(4 * sc4 + 2) * STR + srow] = pa0.z;
                Ad[(4 * sc4 + 3) * STR + srow] = pa0.w;
                Ad[(4 * sc4 + 0) * STR + srow + 64] = pa1.x;
                Ad[(4 * sc4 + 1) * STR + srow + 64] = pa1.y;
                Ad[(4 * sc4 + 2) * STR + srow + 64] = pa1.z;
                Ad[(4 * sc4 + 3) * STR + srow + 64] = pa1.w;
                Bd[(4 * sc4 + 0) * STR + srow] = pb0.x;
                Bd[(4 * sc4 + 1) * STR + srow] = pb0.y;
                Bd[(4 * sc4 + 2) * STR + srow] = pb0.z;
                Bd[(4 * sc4 + 3) * STR + srow] = pb0.w;
                Bd[(4 * sc4 + 0) * STR + srow + 64] = pb1.x;
                Bd[(4 * sc4 + 1) * STR + srow + 64] = pb1.y;
                Bd[(4 * sc4 + 2) * STR + srow + 64] = pb1.z;
                Bd[(4 * sc4 + 3) * STR + srow + 64] = pb1.w;
            }
            __syncthreads();
        }

        // ---- two-phase epilogue + selection (dbuf holds 64 rows) ----
#pragma unroll 1
        for (int hph = 0; hph < 2; ++hph) {
#pragma unroll
            for (int rr = 0; rr < 4; ++rr) {
                int   r  = 4 * hph + rr;
                int   i  = ty + 16 * r;
                float si = sqi[i];
                float* drow = &dbuf[(i - 64 * hph) * DSTR];
#pragma unroll
                for (int c = 0; c < 4; ++c) {
                    float lo, hi;
                    asm("mov.b64 {%0, %1}, %2;" : "=f"(lo), "=f"(hi) : "l"(acc2[r][c]));
                    int j0 = 2 * tx + 32 * c;
                    drow[j0]     = si + sqj[j0]     - 2.f * lo;
                    drow[j0 + 1] = si + sqj[j0 + 1] - 2.f * hi;
                }
            }
            __syncthreads();

            if (tid < 64) {
                const float* drow = &dbuf[tid * DSTR];
                int rowg = tid + 64 * hph;
                float w = hph ? worst1 : worst0;
                for (int j = 0; j < TN; ++j) {
                    float d = drow[j];
                    if (d < w) {
                        int jg = jt + j;
                        int t;
#pragma unroll
                        for (t = K_NN - 1; t >= 1; --t) {
                            float ht = hd[(t - 1) * TM + rowg];
                            if (ht > d) {
                                hd[t * TM + rowg]  = ht;
                                hix[t * TM + rowg] = hix[(t - 1) * TM + rowg];
                            } else {
                                hd[t * TM + rowg]  = d;
                                hix[t * TM + rowg] = jg;
                                break;
                            }
                        }
                        if (t == 0) { hd[rowg] = d; hix[rowg] = jg; }
                        w = hd[(K_NN - 1) * TM + rowg];
                    }
                }
                if (hph) worst1 = w; else worst0 = w;
            }
            __syncthreads();
        }
    }

    if (tid < TM) {
        size_t row  = (size_t)b * L + i0 + tid;
        float  srcv = (float)row;
        float* dd = out_d + row * K_NN;
#pragma unroll
        for (int t = 0; t < K_NN; ++t) dd[t] = hd[t * TM + tid];
        if (write_idx) {
            float* ds = out_s + row * K_NN;
            float* dt = out_t + row * K_NN;
#pragma unroll
            for (int t = 0; t < K_NN; ++t) {
                ds[t] = srcv;
                dt[t] = (float)((size_t)b * L + hix[t * TM + tid]);
            }
        }
    }
}

// ---------------------------------------------------------------------------
extern "C" void kernel_launch(void* const* d_in, const int* in_sizes, int n_in,
                              void* d_out, int out_size) {
    const float* h = (const float*)d_in[0];
    int B = in_sizes[1];
    int n_rows = in_sizes[0] / D_DIM;
    int L = n_rows / B;

    float* out_d = (float*)d_out;
    size_t Nd = (size_t)n_rows * K_NN;
    int three = (size_t)out_size >= 3 * Nd;
    float* out_s = three ? out_d + Nd : out_d;
    float* out_t = three ? out_d + 2 * Nd : out_d;

    size_t smem = (size_t)(4 * KCB * STR + 64 * DSTR + 2 * K_NN * TM + TM + TN) * sizeof(float);
    cudaFuncSetAttribute(knn_kernel, cudaFuncAttributeMaxDynamicSharedMemorySize, (int)smem);

    sqnorm_kernel<<<(n_rows + 7) / 8, 256>>>(h, n_rows);
    dim3 grid(L / TM, B);
    knn_kernel<<<grid, THREADS, smem>>>(h, out_d, out_s, out_t, L, three);
}

// round 5
// speedup vs baseline: 1.3905x; 1.3905x over previous
#include <cuda_runtime.h>
#include <cuda_bf16.h>
#include <stdint.h>

#define D_DIM   256
#define TM      128
#define TN      128
#define KC      32
#define NCH     (D_DIM / KC)
#define K_NN    16
#define THREADS 256
#define ROWB    80            // bytes per staged row (32 bf16 + pad), conflict-free ldmatrix
#define PLANE   (128 * ROWB)  // 10240 B per plane
#define STAGE   (4 * PLANE)   // AHI, ALO, BHI, BLO
#define DSTR    129

// smem byte map
#define OFF_STAGE 0
#define OFF_AHI   0
#define OFF_ALO   PLANE
#define OFF_BHI   (2 * PLANE)
#define OFF_BLO   (3 * PLANE)
#define OFF_DBUF  0                        // overlays stage after k-loop
#define OFF_HD    (2 * STAGE)              // 81920
#define OFF_HIX   (OFF_HD + K_NN * TM * 4)
#define OFF_SQI   (OFF_HIX + K_NN * TM * 4)
#define OFF_SQJ   (OFF_SQI + TM * 4)
#define SMEM_TOT  (OFF_SQJ + TN * 4)

__device__ float g_sq[1 << 17];

__device__ __forceinline__ uint32_t smem_u32(const void* p) {
    uint32_t a;
    asm("{ .reg .u64 t; cvta.to.shared.u64 t, %1; cvt.u32.u64 %0, t; }" : "=r"(a) : "l"(p));
    return a;
}

__device__ __forceinline__ void ldm_x4(uint32_t* r, uint32_t addr) {
    asm volatile("ldmatrix.sync.aligned.m8n8.x4.shared.b16 {%0,%1,%2,%3}, [%4];"
                 : "=r"(r[0]), "=r"(r[1]), "=r"(r[2]), "=r"(r[3]) : "r"(addr));
}

__device__ __forceinline__ void mma_bf16(float* c, const uint32_t* a, uint32_t b0, uint32_t b1) {
    asm volatile(
        "mma.sync.aligned.m16n8k16.row.col.f32.bf16.bf16.f32 "
        "{%0,%1,%2,%3},{%4,%5,%6,%7},{%8,%9},{%0,%1,%2,%3};"
        : "+f"(c[0]), "+f"(c[1]), "+f"(c[2]), "+f"(c[3])
        : "r"(a[0]), "r"(a[1]), "r"(a[2]), "r"(a[3]), "r"(b0), "r"(b1));
}

__device__ __forceinline__ uint32_t pk(__nv_bfloat16 a, __nv_bfloat16 b) {
    return (uint32_t)__bfloat16_as_ushort(a) | ((uint32_t)__bfloat16_as_ushort(b) << 16);
}

// split-convert a float4 into hi/lo bf16x2 pairs, store to plane
__device__ __forceinline__ void store_split(char* smp, uint32_t arr, int row, int kg, float4 v) {
    __nv_bfloat16 h0 = __float2bfloat16(v.x), h1 = __float2bfloat16(v.y);
    __nv_bfloat16 h2 = __float2bfloat16(v.z), h3 = __float2bfloat16(v.w);
    __nv_bfloat16 l0 = __float2bfloat16(v.x - __bfloat162float(h0));
    __nv_bfloat16 l1 = __float2bfloat16(v.y - __bfloat162float(h1));
    __nv_bfloat16 l2 = __float2bfloat16(v.z - __bfloat162float(h2));
    __nv_bfloat16 l3 = __float2bfloat16(v.w - __bfloat162float(h3));
    uint32_t off = arr + (uint32_t)row * ROWB + (uint32_t)kg * 8;
    *(uint2*)(smp + off)         = make_uint2(pk(h0, h1), pk(h2, h3));
    *(uint2*)(smp + off + PLANE) = make_uint2(pk(l0, l1), pk(l2, l3));
}

// ---------------------------------------------------------------------------
__global__ void sqnorm_kernel(const float* __restrict__ h, int n_rows) {
    int row  = blockIdx.x * 8 + (threadIdx.x >> 5);
    int lane = threadIdx.x & 31;
    if (row >= n_rows) return;
    const float4* h4 = (const float4*)(h + (size_t)row * D_DIM);
    float s = 0.f;
#pragma unroll
    for (int p = 0; p < 2; ++p) {
        float4 v = h4[lane + 32 * p];
        s += v.x * v.x + v.y * v.y + v.z * v.z + v.w * v.w;
    }
#pragma unroll
    for (int o = 16; o > 0; o >>= 1)
        s += __shfl_xor_sync(0xffffffffu, s, o);
    if (lane == 0) g_sq[row] = s;
}

// ---------------------------------------------------------------------------
// HMMA bf16 (3-product split) distance GEMM + fused top-16.
// ---------------------------------------------------------------------------
__global__ void __launch_bounds__(THREADS, 1)
knn_mma(const float* __restrict__ h,
        float* __restrict__ out_d, float* __restrict__ out_s, float* __restrict__ out_t,
        int L, int write_idx) {
    extern __shared__ char sm[];
    const uint32_t sb = smem_u32(sm);
    float* dbuf = (float*)(sm + OFF_DBUF);
    float* hd   = (float*)(sm + OFF_HD);
    int*   hix  = (int*)(sm + OFF_HIX);
    float* sqi  = (float*)(sm + OFF_SQI);
    float* sqj  = (float*)(sm + OFF_SQJ);

    const int b    = blockIdx.y;
    const int i0   = blockIdx.x * TM;
    const int tid  = threadIdx.x;
    const int lane = tid & 31;
    const int wid  = tid >> 5;
    const int wm   = wid >> 2;          // 0..1
    const int wn   = wid & 3;           // 0..3
    const float* hb = h + (size_t)b * L * D_DIM;

    if (tid < TM) {
        sqi[tid] = g_sq[(size_t)b * L + i0 + tid];
#pragma unroll
        for (int t = 0; t < K_NN; ++t) { hd[t * TM + tid] = 3.4e38f; hix[t * TM + tid] = 0; }
    }
    float worst = 3.4e38f;

    // ldmatrix relative addresses
    const int lanem = lane & 15;
    const int laneh = (lane >> 4) * 16;
    uint32_t a_rel[4], b_rel[2];
#pragma unroll
    for (int mi = 0; mi < 4; ++mi)
        a_rel[mi] = sb + OFF_AHI + (uint32_t)(wm * 64 + 16 * mi + lanem) * ROWB + laneh;
#pragma unroll
    for (int g = 0; g < 2; ++g)
        b_rel[g] = sb + OFF_BHI + (uint32_t)(wn * 32 + 16 * g + lanem) * ROWB + laneh;

    const int srow = tid >> 3;          // 0..31 (+32p)
    const int skg  = tid & 7;

    for (int jt = 0; jt < L; jt += TN) {
        __syncthreads();                // prev scan done; dbuf/sqj reusable
        if (tid < TN) sqj[tid] = g_sq[(size_t)b * L + jt + tid];

        float acc[4][4][4];
#pragma unroll
        for (int mi = 0; mi < 4; ++mi)
#pragma unroll
            for (int ni = 0; ni < 4; ++ni)
#pragma unroll
                for (int q = 0; q < 4; ++q) acc[mi][ni][q] = 0.f;

        // stage chunk 0 into buffer 0
#pragma unroll
        for (int p = 0; p < 4; ++p) {
            int row = srow + 32 * p;
            float4 va = *(const float4*)(hb + (size_t)(i0 + row) * D_DIM + skg * 4);
            float4 vb = *(const float4*)(hb + (size_t)(jt + row) * D_DIM + skg * 4);
            store_split(sm, OFF_AHI, row, skg, va);
            store_split(sm, OFF_BHI, row, skg, vb);
        }
        __syncthreads();

#pragma unroll 1
        for (int c = 0; c < NCH; ++c) {
            const uint32_t bufo = (uint32_t)(c & 1) * STAGE;

            float4 pa[4], pb[4];
            if (c < NCH - 1) {
                int kb = (c + 1) * KC;
#pragma unroll
                for (int p = 0; p < 4; ++p) {
                    int row = srow + 32 * p;
                    pa[p] = *(const float4*)(hb + (size_t)(i0 + row) * D_DIM + kb + skg * 4);
                    pb[p] = *(const float4*)(hb + (size_t)(jt + row) * D_DIM + kb + skg * 4);
                }
            }

#pragma unroll
            for (int ks = 0; ks < 2; ++ks) {
                const uint32_t ko = bufo + (uint32_t)ks * 32;
                uint32_t ahi[4][4], alo[4][4], bh[2][4], bl[2][4];
#pragma unroll
                for (int mi = 0; mi < 4; ++mi) {
                    ldm_x4(ahi[mi], a_rel[mi] + ko);
                    ldm_x4(alo[mi], a_rel[mi] + ko + PLANE);
                }
#pragma unroll
                for (int g = 0; g < 2; ++g) {
                    ldm_x4(bh[g], b_rel[g] + ko);
                    ldm_x4(bl[g], b_rel[g] + ko + PLANE);
                }
                // hh
#pragma unroll
                for (int mi = 0; mi < 4; ++mi)
#pragma unroll
                    for (int ni = 0; ni < 4; ++ni)
                        mma_bf16(acc[mi][ni], ahi[mi], bh[ni >> 1][ni & 1], bh[ni >> 1][(ni & 1) + 2]);
                // hi * lo
#pragma unroll
                for (int mi = 0; mi < 4; ++mi)
#pragma unroll
                    for (int ni = 0; ni < 4; ++ni)
                        mma_bf16(acc[mi][ni], ahi[mi], bl[ni >> 1][ni & 1], bl[ni >> 1][(ni & 1) + 2]);
                // lo * hi
#pragma unroll
                for (int mi = 0; mi < 4; ++mi)
#pragma unroll
                    for (int ni = 0; ni < 4; ++ni)
                        mma_bf16(acc[mi][ni], alo[mi], bh[ni >> 1][ni & 1], bh[ni >> 1][(ni & 1) + 2]);
            }

            if (c < NCH - 1) {
                const uint32_t nb = (uint32_t)((c + 1) & 1) * STAGE;
#pragma unroll
                for (int p = 0; p < 4; ++p) {
                    int row = srow + 32 * p;
                    store_split(sm, nb + OFF_AHI, row, skg, pa[p]);
                    store_split(sm, nb + OFF_BHI, row, skg, pb[p]);
                }
            }
            __syncthreads();
        }

        // epilogue: distances into dbuf (overlays stage smem)
#pragma unroll
        for (int mi = 0; mi < 4; ++mi) {
            int   r0  = wm * 64 + mi * 16 + (lane >> 2);
            float si0 = sqi[r0], si1 = sqi[r0 + 8];
#pragma unroll
            for (int ni = 0; ni < 4; ++ni) {
                int cl = wn * 32 + ni * 8 + 2 * (lane & 3);
                float sj0 = sqj[cl], sj1 = sqj[cl + 1];
                dbuf[r0 * DSTR + cl]           = si0 + sj0 - 2.f * acc[mi][ni][0];
                dbuf[r0 * DSTR + cl + 1]       = si0 + sj1 - 2.f * acc[mi][ni][1];
                dbuf[(r0 + 8) * DSTR + cl]     = si1 + sj0 - 2.f * acc[mi][ni][2];
                dbuf[(r0 + 8) * DSTR + cl + 1] = si1 + sj1 - 2.f * acc[mi][ni][3];
            }
        }
        __syncthreads();

        // streaming top-16 (ascending j, tie-stable)
        if (tid < TM) {
            const float* drow = &dbuf[tid * DSTR];
            float w = worst;
            for (int j = 0; j < TN; ++j) {
                float d = drow[j];
                if (d < w) {
                    int jg = jt + j;
                    int t;
#pragma unroll
                    for (t = K_NN - 1; t >= 1; --t) {
                        float ht = hd[(t - 1) * TM + tid];
                        if (ht > d) {
                            hd[t * TM + tid]  = ht;
                            hix[t * TM + tid] = hix[(t - 1) * TM + tid];
                        } else {
                            hd[t * TM + tid]  = d;
                            hix[t * TM + tid] = jg;
                            break;
                        }
                    }
                    if (t == 0) { hd[tid] = d; hix[tid] = jg; }
                    w = hd[(K_NN - 1) * TM + tid];
                }
            }
            worst = w;
        }
    }
    __syncthreads();

    if (tid < TM) {
        size_t row  = (size_t)b * L + i0 + tid;
        float  srcv = (float)row;
        float* dd = out_d + row * K_NN;
#pragma unroll
        for (int t = 0; t < K_NN; ++t) dd[t] = hd[t * TM + tid];
        if (write_idx) {
            float* ds = out_s + row * K_NN;
            float* dt = out_t + row * K_NN;
#pragma unroll
            for (int t = 0; t < K_NN; ++t) {
                ds[t] = srcv;
                dt[t] = (float)((size_t)b * L + hix[t * TM + tid]);
            }
        }
    }
}

// ---------------------------------------------------------------------------
extern "C" void kernel_launch(void* const* d_in, const int* in_sizes, int n_in,
                              void* d_out, int out_size) {
    const float* h = (const float*)d_in[0];
    int B = in_sizes[1];
    int n_rows = in_sizes[0] / D_DIM;
    int L = n_rows / B;

    float* out_d = (float*)d_out;
    size_t Nd = (size_t)n_rows * K_NN;
    int three = (size_t)out_size >= 3 * Nd;
    float* out_s = three ? out_d + Nd : out_d;
    float* out_t = three ? out_d + 2 * Nd : out_d;

    cudaFuncSetAttribute(knn_mma, cudaFuncAttributeMaxDynamicSharedMemorySize, SMEM_TOT);

    sqnorm_kernel<<<(n_rows + 7) / 8, 256>>>(h, n_rows);
    dim3 grid(L / TM, B);
    knn_mma<<<grid, THREADS, SMEM_TOT>>>(h, out_d, out_s, out_t, L, three);
}

// round 6
// speedup vs baseline: 1.4260x; 1.0255x over previous
#include <cuda_runtime.h>
#include <cuda_bf16.h>
#include <stdint.h>

#define D_DIM   256
#define TM      128
#define TN      128
#define KC      32
#define NCH     (D_DIM / KC)
#define K_NN    16
#define THREADS 512
#define ROWB    80              // 64B data + 16 pad, 16B-aligned rows
#define PLANE   (128 * ROWB)    // 10240 B
#define STAGE   (4 * PLANE)     // Ahi, Alo, Bhi, Blo = 40960 B
#define DSTR    129

#define OFF_HD    (2 * STAGE)               // 81920
#define OFF_HIX   (OFF_HD + K_NN * TM * 4)
#define OFF_SQI   (OFF_HIX + K_NN * TM * 4)
#define OFF_SQJ   (OFF_SQI + TM * 4)
#define SMEM_TOT  (OFF_SQJ + TN * 4)

__device__ float g_sq[1 << 17];
__device__ __nv_bfloat16 g_hi[1 << 24];
__device__ __nv_bfloat16 g_lo[1 << 24];

__device__ __forceinline__ uint32_t smem_u32(const void* p) {
    uint32_t a;
    asm("{ .reg .u64 t; cvta.to.shared.u64 t, %1; cvt.u32.u64 %0, t; }" : "=r"(a) : "l"(p));
    return a;
}
__device__ __forceinline__ void ldm_x4(uint32_t* r, uint32_t addr) {
    asm volatile("ldmatrix.sync.aligned.m8n8.x4.shared.b16 {%0,%1,%2,%3}, [%4];"
                 : "=r"(r[0]), "=r"(r[1]), "=r"(r[2]), "=r"(r[3]) : "r"(addr));
}
__device__ __forceinline__ void mma_bf16(float* c, const uint32_t* a, uint32_t b0, uint32_t b1) {
    asm volatile(
        "mma.sync.aligned.m16n8k16.row.col.f32.bf16.bf16.f32 "
        "{%0,%1,%2,%3},{%4,%5,%6,%7},{%8,%9},{%0,%1,%2,%3};"
        : "+f"(c[0]), "+f"(c[1]), "+f"(c[2]), "+f"(c[3])
        : "r"(a[0]), "r"(a[1]), "r"(a[2]), "r"(a[3]), "r"(b0), "r"(b1));
}
__device__ __forceinline__ void cp16(uint32_t dst, const void* src) {
    asm volatile("cp.async.ca.shared.global [%0], [%1], 16;" :: "r"(dst), "l"(src));
}

// ---------------------------------------------------------------------------
__global__ void sqnorm_kernel(const float* __restrict__ h, int n_rows) {
    int row  = blockIdx.x * 8 + (threadIdx.x >> 5);
    int lane = threadIdx.x & 31;
    if (row >= n_rows) return;
    const float4* h4 = (const float4*)(h + (size_t)row * D_DIM);
    float s = 0.f;
#pragma unroll
    for (int p = 0; p < 2; ++p) {
        float4 v = h4[lane + 32 * p];
        s += v.x * v.x + v.y * v.y + v.z * v.z + v.w * v.w;
    }
#pragma unroll
    for (int o = 16; o > 0; o >>= 1)
        s += __shfl_xor_sync(0xffffffffu, s, o);
    if (lane == 0) g_sq[row] = s;
}

// precompute bf16 hi/lo split planes
__global__ void split_kernel(const float* __restrict__ h, int n4) {
    int idx = blockIdx.x * blockDim.x + threadIdx.x;
    if (idx >= n4) return;
    float4 v = ((const float4*)h)[idx];
    __nv_bfloat16 h0 = __float2bfloat16(v.x), h1 = __float2bfloat16(v.y);
    __nv_bfloat16 h2 = __float2bfloat16(v.z), h3 = __float2bfloat16(v.w);
    __nv_bfloat162* hp = (__nv_bfloat162*)g_hi;
    __nv_bfloat162* lp = (__nv_bfloat162*)g_lo;
    hp[2 * idx]     = __nv_bfloat162(h0, h1);
    hp[2 * idx + 1] = __nv_bfloat162(h2, h3);
    lp[2 * idx]     = __nv_bfloat162(__float2bfloat16(v.x - __bfloat162float(h0)),
                                     __float2bfloat16(v.y - __bfloat162float(h1)));
    lp[2 * idx + 1] = __nv_bfloat162(__float2bfloat16(v.z - __bfloat162float(h2)),
                                     __float2bfloat16(v.w - __bfloat162float(h3)));
}

// ---------------------------------------------------------------------------
// HMMA bf16 3-product distance GEMM + fused top-16. 16 warps, cp.async staging.
// ---------------------------------------------------------------------------
__global__ void __launch_bounds__(THREADS, 1)
knn_mma(float* __restrict__ out_d, float* __restrict__ out_s, float* __restrict__ out_t,
        int L, int write_idx) {
    extern __shared__ char sm[];
    const uint32_t sb = smem_u32(sm);
    float* dbuf = (float*)sm;               // overlays stage buffers
    float* hd   = (float*)(sm + OFF_HD);
    int*   hix  = (int*)(sm + OFF_HIX);
    float* sqi  = (float*)(sm + OFF_SQI);
    float* sqj  = (float*)(sm + OFF_SQJ);

    const int b    = blockIdx.y;
    const int i0   = blockIdx.x * TM;
    const int tid  = threadIdx.x;
    const int lane = tid & 31;
    const int wid  = tid >> 5;
    const int wm   = wid >> 2;              // 0..3 -> m offset 32*wm
    const int wn   = wid & 3;               // 0..3 -> n offset 32*wn
    const size_t rowbase = (size_t)b * L;

    if (tid < TM) {
        sqi[tid] = g_sq[rowbase + i0 + tid];
#pragma unroll
        for (int t = 0; t < K_NN; ++t) { hd[t * TM + tid] = 3.4e38f; hix[t * TM + tid] = 0; }
    }
    float worst = 3.4e38f;

    // ldmatrix relative addresses (within a stage buffer)
    const int lanem = lane & 15;
    const int laneh = (lane >> 4) * 16;
    uint32_t a_rel[2], b_rel[2];
#pragma unroll
    for (int mi = 0; mi < 2; ++mi)
        a_rel[mi] = sb + (uint32_t)(wm * 32 + 16 * mi + lanem) * ROWB + laneh;           // Ahi plane 0
#pragma unroll
    for (int g = 0; g < 2; ++g)
        b_rel[g] = sb + 2 * PLANE + (uint32_t)(wn * 32 + 16 * g + lanem) * ROWB + laneh; // Bhi plane 2

    // cp.async staging map: 2048 16B segments, 4 per thread
    const int s_plane = tid >> 7;           // 0..3  (Ahi,Alo,Bhi,Blo)
    const int s_r     = (tid >> 2) & 31;    // +32p
    const int s_seg   = tid & 3;

    for (int jt = 0; jt < L; jt += TN) {
        __syncthreads();                    // prev scan done; stage area reusable
        if (tid < TN) sqj[tid] = g_sq[rowbase + jt + tid];

        float acc[2][4][4];
#pragma unroll
        for (int mi = 0; mi < 2; ++mi)
#pragma unroll
            for (int ni = 0; ni < 4; ++ni)
#pragma unroll
                for (int q = 0; q < 4; ++q) acc[mi][ni][q] = 0.f;

        // stage chunk 0 into buf 0
#pragma unroll
        for (int p = 0; p < 4; ++p) {
            int r = s_r + 32 * p;
            const __nv_bfloat16* gp = (s_plane & 1) ? g_lo : g_hi;
            size_t row = rowbase + ((s_plane < 2) ? (i0 + r) : (jt + r));
            cp16(sb + (uint32_t)s_plane * PLANE + (uint32_t)r * ROWB + (uint32_t)s_seg * 16,
                 gp + row * D_DIM + s_seg * 8);
        }
        asm volatile("cp.async.commit_group;" ::: "memory");

#pragma unroll 1
        for (int c = 0; c < NCH; ++c) {
            const uint32_t bufo = (uint32_t)(c & 1) * STAGE;
            if (c + 1 < NCH) {
                int kb = (c + 1) * KC;
                const uint32_t nb = (uint32_t)((c + 1) & 1) * STAGE;
#pragma unroll
                for (int p = 0; p < 4; ++p) {
                    int r = s_r + 32 * p;
                    const __nv_bfloat16* gp = (s_plane & 1) ? g_lo : g_hi;
                    size_t row = rowbase + ((s_plane < 2) ? (i0 + r) : (jt + r));
                    cp16(nb + sb + (uint32_t)s_plane * PLANE + (uint32_t)r * ROWB + (uint32_t)s_seg * 16,
                         gp + row * D_DIM + kb + s_seg * 8);
                }
                asm volatile("cp.async.commit_group;" ::: "memory");
                asm volatile("cp.async.wait_group 1;" ::: "memory");
            } else {
                asm volatile("cp.async.wait_group 0;" ::: "memory");
            }
            __syncthreads();                // chunk c visible

#pragma unroll
            for (int ks = 0; ks < 2; ++ks) {
                const uint32_t ko = bufo + (uint32_t)ks * 32;
                uint32_t ahi[2][4], alo[2][4], bh[2][4], bl[2][4];
#pragma unroll
                for (int mi = 0; mi < 2; ++mi) {
                    ldm_x4(ahi[mi], a_rel[mi] + ko);
                    ldm_x4(alo[mi], a_rel[mi] + ko + PLANE);
                }
#pragma unroll
                for (int g = 0; g < 2; ++g) {
                    ldm_x4(bh[g], b_rel[g] + ko);
                    ldm_x4(bl[g], b_rel[g] + ko + PLANE);
                }
#pragma unroll
                for (int mi = 0; mi < 2; ++mi)
#pragma unroll
                    for (int ni = 0; ni < 4; ++ni) {
                        mma_bf16(acc[mi][ni], ahi[mi], bh[ni >> 1][ni & 1], bh[ni >> 1][(ni & 1) + 2]);
                        mma_bf16(acc[mi][ni], ahi[mi], bl[ni >> 1][ni & 1], bl[ni >> 1][(ni & 1) + 2]);
                        mma_bf16(acc[mi][ni], alo[mi], bh[ni >> 1][ni & 1], bh[ni >> 1][(ni & 1) + 2]);
                    }
            }
            __syncthreads();                // all reads done before buf reuse
        }

        // epilogue: distances into dbuf (overlays stage smem)
#pragma unroll
        for (int mi = 0; mi < 2; ++mi) {
            int   r0  = wm * 32 + mi * 16 + (lane >> 2);
            float si0 = sqi[r0], si1 = sqi[r0 + 8];
#pragma unroll
            for (int ni = 0; ni < 4; ++ni) {
                int cl = wn * 32 + ni * 8 + 2 * (lane & 3);
                float sj0 = sqj[cl], sj1 = sqj[cl + 1];
                dbuf[r0 * DSTR + cl]           = si0 + sj0 - 2.f * acc[mi][ni][0];
                dbuf[r0 * DSTR + cl + 1]       = si0 + sj1 - 2.f * acc[mi][ni][1];
                dbuf[(r0 + 8) * DSTR + cl]     = si1 + sj0 - 2.f * acc[mi][ni][2];
                dbuf[(r0 + 8) * DSTR + cl + 1] = si1 + sj1 - 2.f * acc[mi][ni][3];
            }
        }
        __syncthreads();

        // streaming top-16 (ascending j, tie-stable)
        if (tid < TM) {
            const float* drow = &dbuf[tid * DSTR];
            float w = worst;
            for (int j = 0; j < TN; ++j) {
                float d = drow[j];
                if (d < w) {
                    int jg = jt + j;
                    int t;
#pragma unroll
                    for (t = K_NN - 1; t >= 1; --t) {
                        float ht = hd[(t - 1) * TM + tid];
                        if (ht > d) {
                            hd[t * TM + tid]  = ht;
                            hix[t * TM + tid] = hix[(t - 1) * TM + tid];
                        } else {
                            hd[t * TM + tid]  = d;
                            hix[t * TM + tid] = jg;
                            break;
                        }
                    }
                    if (t == 0) { hd[tid] = d; hix[tid] = jg; }
                    w = hd[(K_NN - 1) * TM + tid];
                }
            }
            worst = w;
        }
    }
    __syncthreads();

    if (tid < TM) {
        size_t row  = rowbase + i0 + tid;
        float  srcv = (float)row;
        float* dd = out_d + row * K_NN;
#pragma unroll
        for (int t = 0; t < K_NN; ++t) dd[t] = hd[t * TM + tid];
        if (write_idx) {
            float* ds = out_s + row * K_NN;
            float* dt = out_t + row * K_NN;
#pragma unroll
            for (int t = 0; t < K_NN; ++t) {
                ds[t] = srcv;
                dt[t] = (float)(rowbase + hix[t * TM + tid]);
            }
        }
    }
}

// ---------------------------------------------------------------------------
extern "C" void kernel_launch(void* const* d_in, const int* in_sizes, int n_in,
                              void* d_out, int out_size) {
    const float* h = (const float*)d_in[0];
    int B = in_sizes[1];
    int n_rows = in_sizes[0] / D_DIM;
    int L = n_rows / B;

    float* out_d = (float*)d_out;
    size_t Nd = (size_t)n_rows * K_NN;
    int three = (size_t)out_size >= 3 * Nd;
    float* out_s = three ? out_d + Nd : out_d;
    float* out_t = three ? out_d + 2 * Nd : out_d;

    cudaFuncSetAttribute(knn_mma, cudaFuncAttributeMaxDynamicSharedMemorySize, SMEM_TOT);

    int n4 = in_sizes[0] / 4;
    sqnorm_kernel<<<(n_rows + 7) / 8, 256>>>(h, n_rows);
    split_kernel<<<(n4 + 255) / 256, 256>>>(h, n4);
    dim3 grid(L / TM, B);
    knn_mma<<<grid, THREADS, SMEM_TOT>>>(out_d, out_s, out_t, L, three);
}

// round 7
// speedup vs baseline: 2.8497x; 1.9984x over previous
#include <cuda_runtime.h>
#include <cuda_bf16.h>
#include <stdint.h>

#define D_DIM   256
#define TM      128
#define TN      128
#define KC      32
#define NCH     (D_DIM / KC)
#define K_NN    16
#define THREADS 256
#define ROWB    80
#define PLANE   (128 * ROWB)     // 10240 B
#define STAGE   (4 * PLANE)      // 40960 B
#define DSTR    129

#define OFF_SQI   (2 * STAGE)              // 81920
#define OFF_SQJ   (OFF_SQI + TM * 4)
#define SMEM_TOT  (OFF_SQJ + TN * 4)       // 82944

__device__ float g_sq[1 << 17];
__device__ __nv_bfloat16 g_hi[1 << 24];
__device__ __nv_bfloat16 g_lo[1 << 24];
__device__ float g_pd[1 << 23];            // partial top-k dists
__device__ int   g_pi[1 << 23];            // partial top-k seg-local idx

__device__ __forceinline__ uint32_t smem_u32(const void* p) {
    uint32_t a;
    asm("{ .reg .u64 t; cvta.to.shared.u64 t, %1; cvt.u32.u64 %0, t; }" : "=r"(a) : "l"(p));
    return a;
}
__device__ __forceinline__ void ldm_x4(uint32_t* r, uint32_t addr) {
    asm volatile("ldmatrix.sync.aligned.m8n8.x4.shared.b16 {%0,%1,%2,%3}, [%4];"
                 : "=r"(r[0]), "=r"(r[1]), "=r"(r[2]), "=r"(r[3]) : "r"(addr));
}
__device__ __forceinline__ void mma_bf16(float* c, const uint32_t* a, uint32_t b0, uint32_t b1) {
    asm volatile(
        "mma.sync.aligned.m16n8k16.row.col.f32.bf16.bf16.f32 "
        "{%0,%1,%2,%3},{%4,%5,%6,%7},{%8,%9},{%0,%1,%2,%3};"
        : "+f"(c[0]), "+f"(c[1]), "+f"(c[2]), "+f"(c[3])
        : "r"(a[0]), "r"(a[1]), "r"(a[2]), "r"(a[3]), "r"(b0), "r"(b1));
}
__device__ __forceinline__ void cp16(uint32_t dst, const void* src) {
    asm volatile("cp.async.ca.shared.global [%0], [%1], 16;" :: "r"(dst), "l"(src));
}

// ---------------------------------------------------------------------------
__global__ void sqnorm_kernel(const float* __restrict__ h, int n_rows) {
    int row  = blockIdx.x * 8 + (threadIdx.x >> 5);
    int lane = threadIdx.x & 31;
    if (row >= n_rows) return;
    const float4* h4 = (const float4*)(h + (size_t)row * D_DIM);
    float s = 0.f;
#pragma unroll
    for (int p = 0; p < 2; ++p) {
        float4 v = h4[lane + 32 * p];
        s += v.x * v.x + v.y * v.y + v.z * v.z + v.w * v.w;
    }
#pragma unroll
    for (int o = 16; o > 0; o >>= 1)
        s += __shfl_xor_sync(0xffffffffu, s, o);
    if (lane == 0) g_sq[row] = s;
}

__global__ void split_kernel(const float* __restrict__ h, int n4) {
    int idx = blockIdx.x * blockDim.x + threadIdx.x;
    if (idx >= n4) return;
    float4 v = ((const float4*)h)[idx];
    __nv_bfloat16 h0 = __float2bfloat16(v.x), h1 = __float2bfloat16(v.y);
    __nv_bfloat16 h2 = __float2bfloat16(v.z), h3 = __float2bfloat16(v.w);
    __nv_bfloat162* hp = (__nv_bfloat162*)g_hi;
    __nv_bfloat162* lp = (__nv_bfloat162*)g_lo;
    hp[2 * idx]     = __nv_bfloat162(h0, h1);
    hp[2 * idx + 1] = __nv_bfloat162(h2, h3);
    lp[2 * idx]     = __nv_bfloat162(__float2bfloat16(v.x - __bfloat162float(h0)),
                                     __float2bfloat16(v.y - __bfloat162float(h1)));
    lp[2 * idx + 1] = __nv_bfloat162(__float2bfloat16(v.z - __bfloat162float(h2)),
                                     __float2bfloat16(v.w - __bfloat162float(h3)));
}

// ---------------------------------------------------------------------------
// One CTA per (i-tile, j-tile). bf16 3-product HMMA + register top-16 partials.
// Warp grid 4x2: warp tile 32(m) x 64(n). grid = (NTJ, NTI, B).
// ---------------------------------------------------------------------------
__global__ void __launch_bounds__(THREADS, 2)
knn_part(int L, int NTJ) {
    extern __shared__ char sm[];
    const uint32_t sb = smem_u32(sm);
    float* dbuf = (float*)sm;               // overlays stage bufs post-k-loop
    float* sqi  = (float*)(sm + OFF_SQI);
    float* sqj  = (float*)(sm + OFF_SQJ);

    const int tj  = blockIdx.x;
    const int i0  = blockIdx.y * TM;
    const int b   = blockIdx.z;
    const int jt  = tj * TN;
    const int tid = threadIdx.x;
    const int lane = tid & 31;
    const int wid  = tid >> 5;
    const int wm   = wid >> 1;              // 0..3  (rows 32*wm)
    const int wn   = wid & 1;               // 0..1  (cols 64*wn)
    const size_t rowbase = (size_t)b * L;

    if (tid < TM) sqi[tid] = g_sq[rowbase + i0 + tid];
    if (tid < TN) sqj[tid] = g_sq[rowbase + jt + tid];

    // ldmatrix base addresses within a stage buffer
    const int lanem = lane & 15;
    const int laneh = (lane >> 4) * 16;
    uint32_t a_rel[2], b_rel[4];
#pragma unroll
    for (int mi = 0; mi < 2; ++mi)
        a_rel[mi] = sb + (uint32_t)(wm * 32 + 16 * mi + lanem) * ROWB + laneh;
#pragma unroll
    for (int g = 0; g < 4; ++g)
        b_rel[g] = sb + 2 * PLANE + (uint32_t)(wn * 64 + 16 * g + lanem) * ROWB + laneh;

    // cp.async map: 2048 16B segs, 8 per thread
    const int s_plane = tid >> 6;           // 0..3 (Ahi,Alo,Bhi,Blo)
    const int s_r     = (tid >> 2) & 15;    // +16p
    const int s_seg   = tid & 3;

    float acc[2][8][4];
#pragma unroll
    for (int mi = 0; mi < 2; ++mi)
#pragma unroll
        for (int ni = 0; ni < 8; ++ni)
#pragma unroll
            for (int q = 0; q < 4; ++q) acc[mi][ni][q] = 0.f;

    // prologue: stage chunk 0
#pragma unroll
    for (int p = 0; p < 8; ++p) {
        int r = s_r + 16 * p;
        const __nv_bfloat16* gp = (s_plane & 1) ? g_lo : g_hi;
        size_t row = rowbase + ((s_plane < 2) ? (i0 + r) : (jt + r));
        cp16(sb + (uint32_t)s_plane * PLANE + (uint32_t)r * ROWB + (uint32_t)s_seg * 16,
             gp + row * D_DIM + s_seg * 8);
    }
    asm volatile("cp.async.commit_group;" ::: "memory");

#pragma unroll 1
    for (int c = 0; c < NCH; ++c) {
        const uint32_t bufo = (uint32_t)(c & 1) * STAGE;
        if (c + 1 < NCH) {
            int kb = (c + 1) * KC;
            const uint32_t nb = (uint32_t)((c + 1) & 1) * STAGE;
#pragma unroll
            for (int p = 0; p < 8; ++p) {
                int r = s_r + 16 * p;
                const __nv_bfloat16* gp = (s_plane & 1) ? g_lo : g_hi;
                size_t row = rowbase + ((s_plane < 2) ? (i0 + r) : (jt + r));
                cp16(nb + sb + (uint32_t)s_plane * PLANE + (uint32_t)r * ROWB + (uint32_t)s_seg * 16,
                     gp + row * D_DIM + kb + s_seg * 8);
            }
            asm volatile("cp.async.commit_group;" ::: "memory");
            asm volatile("cp.async.wait_group 1;" ::: "memory");
        } else {
            asm volatile("cp.async.wait_group 0;" ::: "memory");
        }
        __syncthreads();

#pragma unroll
        for (int ks = 0; ks < 2; ++ks) {
            const uint32_t ko = bufo + (uint32_t)ks * 32;
            uint32_t ahi[2][4], alo[2][4];
#pragma unroll
            for (int mi = 0; mi < 2; ++mi) {
                ldm_x4(ahi[mi], a_rel[mi] + ko);
                ldm_x4(alo[mi], a_rel[mi] + ko + PLANE);
            }
#pragma unroll
            for (int g = 0; g < 4; ++g) {
                uint32_t bh[4], bl[4];
                ldm_x4(bh, b_rel[g] + ko);
                ldm_x4(bl, b_rel[g] + ko + PLANE);
#pragma unroll
                for (int mi = 0; mi < 2; ++mi)
#pragma unroll
                    for (int nn = 0; nn < 2; ++nn) {
                        float* a = acc[mi][2 * g + nn];
                        mma_bf16(a, ahi[mi], bh[nn], bh[nn + 2]);
                        mma_bf16(a, ahi[mi], bl[nn], bl[nn + 2]);
                        mma_bf16(a, alo[mi], bh[nn], bh[nn + 2]);
                    }
            }
        }
        __syncthreads();                    // reads done before buf reuse
    }

    // epilogue: distances into dbuf (overlays stage smem)
#pragma unroll
    for (int mi = 0; mi < 2; ++mi) {
        int   r0  = wm * 32 + mi * 16 + (lane >> 2);
        float si0 = sqi[r0], si1 = sqi[r0 + 8];
#pragma unroll
        for (int ni = 0; ni < 8; ++ni) {
            int cl = wn * 64 + ni * 8 + 2 * (lane & 3);
            float sj0 = sqj[cl], sj1 = sqj[cl + 1];
            dbuf[r0 * DSTR + cl]           = si0 + sj0 - 2.f * acc[mi][ni][0];
            dbuf[r0 * DSTR + cl + 1]       = si0 + sj1 - 2.f * acc[mi][ni][1];
            dbuf[(r0 + 8) * DSTR + cl]     = si1 + sj0 - 2.f * acc[mi][ni][2];
            dbuf[(r0 + 8) * DSTR + cl + 1] = si1 + sj1 - 2.f * acc[mi][ni][3];
        }
    }
    __syncthreads();

    // register-heap partial top-16 over this tile's 128 cols (tie-stable)
    if (tid < TM) {
        float hp[K_NN];
        int   hx[K_NN];
#pragma unroll
        for (int t = 0; t < K_NN; ++t) { hp[t] = 3.4e38f; hx[t] = 0; }
        const float* drow = &dbuf[tid * DSTR];
        float w = 3.4e38f;
#pragma unroll 1
        for (int j = 0; j < TN; ++j) {
            float d = drow[j];
            if (d < w) {
                int jg = jt + j;
#pragma unroll
                for (int t = K_NN - 1; t >= 1; --t) {
                    if (hp[t - 1] > d)      { hp[t] = hp[t - 1]; hx[t] = hx[t - 1]; }
                    else if (hp[t] > d)     { hp[t] = d;         hx[t] = jg; }
                }
                if (hp[0] > d)              { hp[0] = d;         hx[0] = jg; }
                w = hp[K_NN - 1];
            }
        }
        size_t base = ((size_t)(rowbase + i0 + tid) * NTJ + tj) * K_NN;
#pragma unroll
        for (int t = 0; t < K_NN; ++t) {
            g_pd[base + t] = hp[t];
            g_pi[base + t] = hx[t];
        }
    }
}

// ---------------------------------------------------------------------------
// Merge NTJ sorted partial lists per row -> final top-16 (tie-stable).
// ---------------------------------------------------------------------------
__global__ void merge_kernel(float* __restrict__ out_d, float* __restrict__ out_s,
                             float* __restrict__ out_t,
                             int L, int NTJ, int write_idx, int n_rows) {
    int row = blockIdx.x * blockDim.x + threadIdx.x;
    if (row >= n_rows) return;
    float hp[K_NN];
    int   hx[K_NN];
#pragma unroll
    for (int t = 0; t < K_NN; ++t) { hp[t] = 3.4e38f; hx[t] = 0; }
    float w = 3.4e38f;
    size_t base = (size_t)row * NTJ * K_NN;
#pragma unroll 1
    for (int tj = 0; tj < NTJ; ++tj) {
#pragma unroll 1
        for (int t = 0; t < K_NN; ++t) {
            float d = g_pd[base + tj * K_NN + t];
            if (d >= w) break;              // list sorted ascending
            int jg = g_pi[base + tj * K_NN + t];
#pragma unroll
            for (int u = K_NN - 1; u >= 1; --u) {
                if (hp[u - 1] > d)      { hp[u] = hp[u - 1]; hx[u] = hx[u - 1]; }
                else if (hp[u] > d)     { hp[u] = d;         hx[u] = jg; }
            }
            if (hp[0] > d)              { hp[0] = d;         hx[0] = jg; }
            w = hp[K_NN - 1];
        }
    }
    size_t rowbase = (size_t)(row / L) * L;
    float  srcv = (float)row;
    float* dd = out_d + (size_t)row * K_NN;
#pragma unroll
    for (int t = 0; t < K_NN; ++t) dd[t] = hp[t];
    if (write_idx) {
        float* ds = out_s + (size_t)row * K_NN;
        float* dt = out_t + (size_t)row * K_NN;
#pragma unroll
        for (int t = 0; t < K_NN; ++t) {
            ds[t] = srcv;
            dt[t] = (float)(rowbase + hx[t]);
        }
    }
}

// ---------------------------------------------------------------------------
extern "C" void kernel_launch(void* const* d_in, const int* in_sizes, int n_in,
                              void* d_out, int out_size) {
    const float* h = (const float*)d_in[0];
    int B = in_sizes[1];
    int n_rows = in_sizes[0] / D_DIM;
    int L = n_rows / B;
    int NTJ = L / TN;

    float* out_d = (float*)d_out;
    size_t Nd = (size_t)n_rows * K_NN;
    int three = (size_t)out_size >= 3 * Nd;
    float* out_s = three ? out_d + Nd : out_d;
    float* out_t = three ? out_d + 2 * Nd : out_d;

    cudaFuncSetAttribute(knn_part, cudaFuncAttributeMaxDynamicSharedMemorySize, SMEM_TOT);

    int n4 = in_sizes[0] / 4;
    sqnorm_kernel<<<(n_rows + 7) / 8, 256>>>(h, n_rows);
    split_kernel<<<(n4 + 255) / 256, 256>>>(h, n4);
    dim3 grid(NTJ, L / TM, B);
    knn_part<<<grid, THREADS, SMEM_TOT>>>(L, NTJ);
    merge_kernel<<<(n_rows + 255) / 256, 256>>>(out_d, out_s, out_t, L, NTJ, three, n_rows);
}